// round 14
// baseline (speedup 1.0000x reference)
#include <cuda_runtime.h>
#include <cstdint>

#define EPSF 1e-6f
#define L2E  1.44269504088896340736f

constexpr int SI = 3000;
constexpr int SJ = 3000;
constexpr int NLINKS = 500000;
constexpr int BT = 256;
constexpr int GATHER_BLOCKS = (SI + BT - 1) / BT;   // 12
constexpr int NLB = 436;                            // link blocks in k1
constexpr int K1_TOTAL = GATHER_BLOCKS + NLB;       // 448 ~ one wave
constexpr int IT = 4;                               // i's per block-term block (swept optimum)
constexpr int NBI = SI / IT;                        // 750 pure block-term blocks

// ---------------- device scratch (allocation-free) ----------------
__device__ float4 g_zi0[SI], g_zi1[SI];      // gathered zi rows, EPS pre-added
__device__ float  g_na[SI];                  // ||zi+eps||^2
__device__ float  g_bL[SI];                  // beta[si]*log2(e)
__device__ float4 g_q0[SJ], g_q1[SJ];        // gathered -2*zj rows
__device__ float2 g_nbgL[SJ];                // { ||zj||^2, gamma[sj]*log2(e) }
__device__ float  g_part_block[NBI];
__device__ float  g_part_links[NLB];
__device__ int    g_ticket;

__device__ __forceinline__ float warp_sum(float v) {
    #pragma unroll
    for (int o = 16; o > 0; o >>= 1) v += __shfl_xor_sync(0xffffffffu, v, o);
    return v;
}
__device__ __forceinline__ float block_sum(float v) {
    __shared__ float w[BT / 32];
    v = warp_sum(v);
    if ((threadIdx.x & 31) == 0) w[threadIdx.x >> 5] = v;
    __syncthreads();
    if (threadIdx.x < BT / 32) {
        v = w[threadIdx.x];
        #pragma unroll
        for (int o = BT / 64; o > 0; o >>= 1) v += __shfl_xor_sync(0xffu, v, o);
    }
    return v;
}

// ====== kernel 1: gather + prescale + norms  PLUS the entire link term ======
// (links depend only on raw inputs, not on the gather — safe to co-schedule)
__global__ __launch_bounds__(BT) void k1(const float* __restrict__ zi,
                                         const float* __restrict__ zj,
                                         const float* __restrict__ beta,
                                         const float* __restrict__ gamma,
                                         const int*   __restrict__ si,
                                         const int*   __restrict__ sj,
                                         const int*   __restrict__ li,
                                         const int*   __restrict__ lj) {
    if (blockIdx.x < GATHER_BLOCKS) {
        const int t = blockIdx.x * BT + threadIdx.x;
        if (t == 0) g_ticket = 0;
        if (t < SI) {
            const int i = si[t];
            float4 a0 = __ldg((const float4*)&zi[i * 8]);
            float4 a1 = __ldg((const float4*)&zi[i * 8 + 4]);
            a0.x += EPSF; a0.y += EPSF; a0.z += EPSF; a0.w += EPSF;
            a1.x += EPSF; a1.y += EPSF; a1.z += EPSF; a1.w += EPSF;
            g_zi0[t] = a0; g_zi1[t] = a1;
            float na = a0.x * a0.x;
            na = fmaf(a0.y, a0.y, na); na = fmaf(a0.z, a0.z, na); na = fmaf(a0.w, a0.w, na);
            na = fmaf(a1.x, a1.x, na); na = fmaf(a1.y, a1.y, na); na = fmaf(a1.z, a1.z, na);
            na = fmaf(a1.w, a1.w, na);
            g_na[t] = na;
            g_bL[t] = beta[i] * L2E;
        }
        if (t < SJ) {
            const int j = sj[t];
            const float4 b0 = __ldg((const float4*)&zj[j * 8]);
            const float4 b1 = __ldg((const float4*)&zj[j * 8 + 4]);
            float nb = b0.x * b0.x;
            nb = fmaf(b0.y, b0.y, nb); nb = fmaf(b0.z, b0.z, nb); nb = fmaf(b0.w, b0.w, nb);
            nb = fmaf(b1.x, b1.x, nb); nb = fmaf(b1.y, b1.y, nb); nb = fmaf(b1.z, b1.z, nb);
            nb = fmaf(b1.w, b1.w, nb);
            float4 q0, q1;
            q0.x = -2.0f * b0.x; q0.y = -2.0f * b0.y; q0.z = -2.0f * b0.z; q0.w = -2.0f * b0.w;
            q1.x = -2.0f * b1.x; q1.y = -2.0f * b1.y; q1.z = -2.0f * b1.z; q1.w = -2.0f * b1.w;
            g_q0[t] = q0; g_q1[t] = q1;
            g_nbgL[t] = make_float2(nb, gamma[j] * L2E);
        }
        return;
    }

    // ---- link term (exact subtraction form; full chip available during k1) ----
    const int b = blockIdx.x - GATHER_BLOCKS;
    const int stride = NLB * BT;
    float acc = 0.0f;
    for (int e = b * BT + threadIdx.x; e < NLINKS; e += stride) {
        const int i = li[e];
        const int j = lj[e];
        const float4 a0 = __ldg((const float4*)&zi[i * 8]);
        const float4 a1 = __ldg((const float4*)&zi[i * 8 + 4]);
        const float4 b0 = __ldg((const float4*)&zj[j * 8]);
        const float4 b1 = __ldg((const float4*)&zj[j * 8 + 4]);
        float d0 = a0.x - b0.x + EPSF, d1 = a0.y - b0.y + EPSF;
        float d2 = a0.z - b0.z + EPSF, d3 = a0.w - b0.w + EPSF;
        float d4 = a1.x - b1.x + EPSF, d5 = a1.y - b1.y + EPSF;
        float d6 = a1.z - b1.z + EPSF, d7 = a1.w - b1.w + EPSF;
        float s = d0 * d0;
        s = fmaf(d1, d1, s); s = fmaf(d2, d2, s); s = fmaf(d3, d3, s);
        s = fmaf(d4, d4, s); s = fmaf(d5, d5, s); s = fmaf(d6, d6, s);
        s = fmaf(d7, d7, s);
        const float u = rsqrtf(s);
        acc += __ldg(&beta[i]) + __ldg(&gamma[j]) - s * u;
    }
    const float tot = block_sum(acc);
    if (threadIdx.x == 0) g_part_links[b] = tot;
}

// ====== kernel 2: PURE block term (uniform blocks, no L1tex pollution) ======
__global__ __launch_bounds__(BT) void k2(float* __restrict__ out) {
    // ---- 4 i's x all j, scalar norm-trick + sqrt.approx ----
    const int ib = blockIdx.x * IT;

    float4 A0[IT], A1[IT];
    float  na[IT], bL[IT];
    #pragma unroll
    for (int u = 0; u < IT; u++) {
        A0[u] = g_zi0[ib + u];
        A1[u] = g_zi1[ib + u];
        na[u] = g_na[ib + u];
        bL[u] = g_bL[ib + u];
    }
    float acc[IT];
    #pragma unroll
    for (int u = 0; u < IT; u++) acc[u] = 0.0f;

    for (int j = threadIdx.x; j < SJ; j += BT) {
        const float4 q0 = g_q0[j];            // -2*zj
        const float4 q1 = g_q1[j];
        const float2 ng = g_nbgL[j];          // { nb, gL }
        #pragma unroll
        for (int u = 0; u < IT; u++) {
            // s = (na + nb) + a.(-2b): 8-FFMA chain, 4 independent chains over u
            float s = fmaf(A0[u].x, q0.x, na[u] + ng.x);
            s = fmaf(A0[u].y, q0.y, s);
            s = fmaf(A0[u].z, q0.z, s);
            s = fmaf(A0[u].w, q0.w, s);
            s = fmaf(A1[u].x, q1.x, s);
            s = fmaf(A1[u].y, q1.y, s);
            s = fmaf(A1[u].z, q1.z, s);
            s = fmaf(A1[u].w, q1.w, s);
            s = fmaxf(s, 1e-12f);                            // cancellation guard
            float d;
            asm("sqrt.approx.f32 %0, %1;" : "=f"(d) : "f"(s));   // MUFU
            const float t = fmaf(d, -L2E, bL[u] + ng.y);         // log2 domain
            float e;
            asm("ex2.approx.f32 %0, %1;" : "=f"(e) : "f"(t));    // MUFU.EX2
            acc[u] += e;
        }
    }
    const float tot = block_sum(acc[0] + acc[1] + acc[2] + acc[3]);
    if (threadIdx.x == 0) g_part_block[blockIdx.x] = tot;

    // ---- last-finishing block performs the deterministic final reduction ----
    __shared__ int isLast;
    __threadfence();                                   // release our partial
    if (threadIdx.x == 0) isLast = (atomicAdd(&g_ticket, 1) == NBI - 1);
    __syncthreads();
    if (!isLast) return;
    __threadfence();                                   // acquire others' partials

    __shared__ double redB[BT], redL[BT];
    double sb = 0.0, sl = 0.0;
    for (int k = threadIdx.x; k < NBI; k += BT) sb += (double)g_part_block[k];
    for (int k = threadIdx.x; k < NLB; k += BT) sl += (double)g_part_links[k];
    redB[threadIdx.x] = sb;
    redL[threadIdx.x] = sl;
    __syncthreads();
    #pragma unroll
    for (int s2 = BT / 2; s2 > 0; s2 >>= 1) {
        if (threadIdx.x < s2) {
            redB[threadIdx.x] += redB[threadIdx.x + s2];
            redL[threadIdx.x] += redL[threadIdx.x + s2];
        }
        __syncthreads();
    }
    if (threadIdx.x == 0) out[0] = (float)(redL[0] - redB[0]);
}

extern "C" void kernel_launch(void* const* d_in, const int* in_sizes, int n_in,
                              void* d_out, int out_size) {
    const float* latent_zi = (const float*)d_in[0];
    const float* latent_zj = (const float*)d_in[1];
    const float* beta      = (const float*)d_in[2];
    const float* gamma     = (const float*)d_in[3];
    const int*   si        = (const int*)  d_in[4];
    const int*   sj        = (const int*)  d_in[5];
    const int*   li        = (const int*)  d_in[6];
    const int*   lj        = (const int*)  d_in[7];
    float* out = (float*)d_out;

    k1<<<K1_TOTAL, BT>>>(latent_zi, latent_zj, beta, gamma, si, sj, li, lj);
    k2<<<NBI, BT>>>(out);
}

// round 16
// speedup vs baseline: 1.1367x; 1.1367x over previous
#include <cuda_runtime.h>
#include <cstdint>

#define EPSF 1e-6f
#define L2E  1.44269504088896340736f

constexpr int SI = 3000;
constexpr int SJ = 3000;
constexpr int NLINKS = 500000;
constexpr int BT = 128;                             // block-size experiment (was 256 all rounds)
constexpr int GATHER_BLOCKS = (SI + BT - 1) / BT;   // 24
constexpr int IT = 4;                               // swept optimum
constexpr int NBI = SI / IT;                        // 750
constexpr int K2_LINK = 592;                        // link blocks first (128 thr each)
constexpr int K2_TOTAL = K2_LINK + NBI;             // 1342

// ---------------- device scratch (allocation-free) ----------------
__device__ float4 g_zi0[SI], g_zi1[SI];      // gathered zi rows, EPS pre-added
__device__ float  g_na[SI];                  // ||zi+eps||^2
__device__ float  g_bL[SI];                  // beta[si]*log2(e)
__device__ float4 g_q0[SJ], g_q1[SJ];        // gathered -2*zj rows
__device__ float2 g_nbgL[SJ];                // { ||zj||^2, gamma[sj]*log2(e) }
__device__ float  g_part_block[NBI];
__device__ float  g_part_links[K2_LINK];
__device__ int    g_ticket;

__device__ __forceinline__ float warp_sum(float v) {
    #pragma unroll
    for (int o = 16; o > 0; o >>= 1) v += __shfl_xor_sync(0xffffffffu, v, o);
    return v;
}
__device__ __forceinline__ float block_sum(float v) {
    __shared__ float w[BT / 32];
    v = warp_sum(v);
    if ((threadIdx.x & 31) == 0) w[threadIdx.x >> 5] = v;
    __syncthreads();
    if (threadIdx.x < BT / 32) {
        v = w[threadIdx.x];
        #pragma unroll
        for (int o = BT / 64; o > 0; o >>= 1) v += __shfl_xor_sync(0xfu, v, o);
    }
    return v;
}

// ================= kernel 1: gather + prescale + norms =================
__global__ __launch_bounds__(BT) void k1(const float* __restrict__ zi,
                                         const float* __restrict__ zj,
                                         const float* __restrict__ beta,
                                         const float* __restrict__ gamma,
                                         const int*   __restrict__ si,
                                         const int*   __restrict__ sj) {
    const int t = blockIdx.x * BT + threadIdx.x;
    if (t == 0) g_ticket = 0;
    if (t < SI) {
        const int i = si[t];
        float4 a0 = __ldg((const float4*)&zi[i * 8]);
        float4 a1 = __ldg((const float4*)&zi[i * 8 + 4]);
        a0.x += EPSF; a0.y += EPSF; a0.z += EPSF; a0.w += EPSF;
        a1.x += EPSF; a1.y += EPSF; a1.z += EPSF; a1.w += EPSF;
        g_zi0[t] = a0; g_zi1[t] = a1;
        float na = a0.x * a0.x;
        na = fmaf(a0.y, a0.y, na); na = fmaf(a0.z, a0.z, na); na = fmaf(a0.w, a0.w, na);
        na = fmaf(a1.x, a1.x, na); na = fmaf(a1.y, a1.y, na); na = fmaf(a1.z, a1.z, na);
        na = fmaf(a1.w, a1.w, na);
        g_na[t] = na;
        g_bL[t] = beta[i] * L2E;
    }
    if (t < SJ) {
        const int j = sj[t];
        const float4 b0 = __ldg((const float4*)&zj[j * 8]);
        const float4 b1 = __ldg((const float4*)&zj[j * 8 + 4]);
        float nb = b0.x * b0.x;
        nb = fmaf(b0.y, b0.y, nb); nb = fmaf(b0.z, b0.z, nb); nb = fmaf(b0.w, b0.w, nb);
        nb = fmaf(b1.x, b1.x, nb); nb = fmaf(b1.y, b1.y, nb); nb = fmaf(b1.z, b1.z, nb);
        nb = fmaf(b1.w, b1.w, nb);
        float4 q0, q1;
        q0.x = -2.0f * b0.x; q0.y = -2.0f * b0.y; q0.z = -2.0f * b0.z; q0.w = -2.0f * b0.w;
        q1.x = -2.0f * b1.x; q1.y = -2.0f * b1.y; q1.z = -2.0f * b1.z; q1.w = -2.0f * b1.w;
        g_q0[t] = q0; g_q1[t] = q1;
        g_nbgL[t] = make_float2(nb, gamma[j] * L2E);
    }
}

// ====== kernel 2 (BT=128): links (first) + block term + final reduce ======
__global__ __launch_bounds__(BT) void k2(const float* __restrict__ zi,
                                         const float* __restrict__ zj,
                                         const float* __restrict__ beta,
                                         const float* __restrict__ gamma,
                                         const int*   __restrict__ li,
                                         const int*   __restrict__ lj,
                                         float* __restrict__ out) {
    if (blockIdx.x < K2_LINK) {
        // ---- link term (memory-latency bound; exact subtraction form) ----
        const int b = blockIdx.x;
        const int stride = K2_LINK * BT;
        float acc = 0.0f;
        for (int e = b * BT + threadIdx.x; e < NLINKS; e += stride) {
            const int i = li[e];
            const int j = lj[e];
            const float4 a0 = __ldg((const float4*)&zi[i * 8]);
            const float4 a1 = __ldg((const float4*)&zi[i * 8 + 4]);
            const float4 b0 = __ldg((const float4*)&zj[j * 8]);
            const float4 b1 = __ldg((const float4*)&zj[j * 8 + 4]);
            float d0 = a0.x - b0.x + EPSF, d1 = a0.y - b0.y + EPSF;
            float d2 = a0.z - b0.z + EPSF, d3 = a0.w - b0.w + EPSF;
            float d4 = a1.x - b1.x + EPSF, d5 = a1.y - b1.y + EPSF;
            float d6 = a1.z - b1.z + EPSF, d7 = a1.w - b1.w + EPSF;
            float s = d0 * d0;
            s = fmaf(d1, d1, s); s = fmaf(d2, d2, s); s = fmaf(d3, d3, s);
            s = fmaf(d4, d4, s); s = fmaf(d5, d5, s); s = fmaf(d6, d6, s);
            s = fmaf(d7, d7, s);
            const float u = rsqrtf(s);
            acc += __ldg(&beta[i]) + __ldg(&gamma[j]) - s * u;
        }
        const float tot = block_sum(acc);
        if (threadIdx.x == 0) g_part_links[b] = tot;
    } else {
        // ---- sampled block term: 4 i's x all j, scalar norm-trick + sqrt.approx ----
        const int ib = (blockIdx.x - K2_LINK) * IT;

        float4 A0[IT], A1[IT];
        float  na[IT], bL[IT];
        #pragma unroll
        for (int u = 0; u < IT; u++) {
            A0[u] = g_zi0[ib + u];
            A1[u] = g_zi1[ib + u];
            na[u] = g_na[ib + u];
            bL[u] = g_bL[ib + u];
        }
        float acc[IT];
        #pragma unroll
        for (int u = 0; u < IT; u++) acc[u] = 0.0f;

        for (int j = threadIdx.x; j < SJ; j += BT) {
            const float4 q0 = g_q0[j];            // -2*zj
            const float4 q1 = g_q1[j];
            const float2 ng = g_nbgL[j];          // { nb, gL }
            #pragma unroll
            for (int u = 0; u < IT; u++) {
                float s = fmaf(A0[u].x, q0.x, na[u] + ng.x);
                s = fmaf(A0[u].y, q0.y, s);
                s = fmaf(A0[u].z, q0.z, s);
                s = fmaf(A0[u].w, q0.w, s);
                s = fmaf(A1[u].x, q1.x, s);
                s = fmaf(A1[u].y, q1.y, s);
                s = fmaf(A1[u].z, q1.z, s);
                s = fmaf(A1[u].w, q1.w, s);
                s = fmaxf(s, 1e-12f);                            // cancellation guard
                float d;
                asm("sqrt.approx.f32 %0, %1;" : "=f"(d) : "f"(s));   // MUFU
                const float t = fmaf(d, -L2E, bL[u] + ng.y);         // log2 domain
                float e;
                asm("ex2.approx.f32 %0, %1;" : "=f"(e) : "f"(t));    // MUFU.EX2
                acc[u] += e;
            }
        }
        const float tot = block_sum(acc[0] + acc[1] + acc[2] + acc[3]);
        if (threadIdx.x == 0) g_part_block[blockIdx.x - K2_LINK] = tot;
    }

    // ---- last-finishing block performs the deterministic final reduction ----
    __shared__ int isLast;
    __threadfence();                                   // release our partial
    if (threadIdx.x == 0) isLast = (atomicAdd(&g_ticket, 1) == K2_TOTAL - 1);
    __syncthreads();
    if (!isLast) return;
    __threadfence();                                   // acquire others' partials

    __shared__ double redB[BT], redL[BT];
    double sb = 0.0, sl = 0.0;
    for (int k = threadIdx.x; k < NBI; k += BT)     sb += (double)g_part_block[k];
    for (int k = threadIdx.x; k < K2_LINK; k += BT) sl += (double)g_part_links[k];
    redB[threadIdx.x] = sb;
    redL[threadIdx.x] = sl;
    __syncthreads();
    #pragma unroll
    for (int s2 = BT / 2; s2 > 0; s2 >>= 1) {
        if (threadIdx.x < s2) {
            redB[threadIdx.x] += redB[threadIdx.x + s2];
            redL[threadIdx.x] += redL[threadIdx.x + s2];
        }
        __syncthreads();
    }
    if (threadIdx.x == 0) out[0] = (float)(redL[0] - redB[0]);
}

extern "C" void kernel_launch(void* const* d_in, const int* in_sizes, int n_in,
                              void* d_out, int out_size) {
    const float* latent_zi = (const float*)d_in[0];
    const float* latent_zj = (const float*)d_in[1];
    const float* beta      = (const float*)d_in[2];
    const float* gamma     = (const float*)d_in[3];
    const int*   si        = (const int*)  d_in[4];
    const int*   sj        = (const int*)  d_in[5];
    const int*   li        = (const int*)  d_in[6];
    const int*   lj        = (const int*)  d_in[7];
    float* out = (float*)d_out;

    k1<<<GATHER_BLOCKS, BT>>>(latent_zi, latent_zj, beta, gamma, si, sj);
    k2<<<K2_TOTAL, BT>>>(latent_zi, latent_zj, beta, gamma, li, lj, out);
}